// round 3
// baseline (speedup 1.0000x reference)
#include <cuda_runtime.h>

// Problem constants
#define RR 256
#define BB 32
#define TT 32
#define YSZ 64

// Scratch for the stage-1 result x[b, p, q] (B,256,256) fp32 = 8.4 MB.
__device__ float g_x[BB * RR * RR];

// ---------------------------------------------------------------------------
// Stage 1: x[b,p,q] = sum_t Ht[t,p,q] * yt[b,t,p>>2,q>>2]
// Each thread: 4 consecutive q pixels (one q4 cell) x 8 batches, fixed p.
// Ht is read exactly once chip-wide (vectorized float4, amortized over 8 b).
// yt loads are coalesced across the warp (q4 == threadIdx.x contiguous).
// ---------------------------------------------------------------------------
__global__ __launch_bounds__(256) void stage1_kernel(
    const float* __restrict__ yt, const float* __restrict__ Ht) {
  int tx = threadIdx.x;                     // 0..63  -> q4
  int p  = blockIdx.x * 4 + threadIdx.y;    // 0..255
  int bg = blockIdx.y;                      // 0..3 (8 batches each)
  int q0 = tx * 4;
  int p4 = p >> 2;

  float acc[8][4];
#pragma unroll
  for (int i = 0; i < 8; i++)
#pragma unroll
    for (int j = 0; j < 4; j++) acc[i][j] = 0.f;

#pragma unroll 4
  for (int t = 0; t < TT; t++) {
    float4 h = *reinterpret_cast<const float4*>(Ht + ((size_t)t * RR + p) * RR + q0);
    const float* yb = yt + ((size_t)(bg * 8) * TT + t) * (YSZ * YSZ) + p4 * YSZ + tx;
#pragma unroll
    for (int bi = 0; bi < 8; bi++) {
      float yv = yb[(size_t)bi * TT * YSZ * YSZ];
      acc[bi][0] = fmaf(h.x, yv, acc[bi][0]);
      acc[bi][1] = fmaf(h.y, yv, acc[bi][1]);
      acc[bi][2] = fmaf(h.z, yv, acc[bi][2]);
      acc[bi][3] = fmaf(h.w, yv, acc[bi][3]);
    }
  }
#pragma unroll
  for (int bi = 0; bi < 8; bi++) {
    float4 o = make_float4(acc[bi][0], acc[bi][1], acc[bi][2], acc[bi][3]);
    *reinterpret_cast<float4*>(g_x + ((size_t)(bg * 8 + bi) * RR + p) * RR + q0) = o;
  }
}

// ---------------------------------------------------------------------------
// Stage 2: fused conv(1->32,3x3,SAME) -> ReLU -> conv(32->1,3x3,SAME).
// One block = one batch x one 32x32 output tile. x-tile (36x36 halo) in smem.
// Channels processed in 8 groups of 4: relu1 for the group staged in smem
// (34x34 region, covering output coords -1..32), conv2 partials accumulated
// in registers (4 adjacent output px per thread, vectorized smem reads).
// relu1 outside the 256x256 image is forced to 0 (conv2 zero padding).
// ---------------------------------------------------------------------------
__global__ __launch_bounds__(256) void conv_kernel(
    const float* __restrict__ W1, const float* __restrict__ b1,
    const float* __restrict__ W2, const float* __restrict__ b2,
    float* __restrict__ out) {
  __shared__ __align__(16) float xs[36][40];       // x tile + halo2 (col-padded)
  __shared__ __align__(16) float rs[4][34][36];    // relu1, 4-channel group
  __shared__ float w1s[288], w2s[288], b1s[32];

  int tid = threadIdx.x;
  int bb  = blockIdx.z;
  int oy0 = blockIdx.y * 32, ox0 = blockIdx.x * 32;
  const float* xb = g_x + (size_t)bb * RR * RR;

  for (int i = tid; i < 288; i += 256) { w1s[i] = W1[i]; w2s[i] = W2[i]; }
  if (tid < 32) b1s[tid] = b1[tid];

  // Load x tile rows oy0-2..oy0+33, cols ox0-2..ox0+33 (zero outside image)
  for (int i = tid; i < 36 * 36; i += 256) {
    int r = i / 36, c = i - r * 36;
    int gy = oy0 - 2 + r, gx = ox0 - 2 + c;
    float v = 0.f;
    if ((unsigned)gy < 256u && (unsigned)gx < 256u) v = xb[gy * 256 + gx];
    xs[r][c] = v;
  }
  __syncthreads();
  float bias2 = b2[0];

  int oly  = tid >> 3;          // output row in tile 0..31
  int olx0 = (tid & 7) * 4;     // output col base 0..28
  float acc0 = bias2, acc1 = bias2, acc2 = bias2, acc3 = bias2;

  for (int cg = 0; cg < 8; cg++) {
    // conv1 weights for this 4-channel group -> registers
    float w1r[4][9], b1r[4];
#pragma unroll
    for (int cl = 0; cl < 4; cl++) {
      b1r[cl] = b1s[cg * 4 + cl];
#pragma unroll
      for (int k = 0; k < 9; k++) w1r[cl][k] = w1s[(cg * 4 + cl) * 9 + k];
    }
    if (cg) __syncthreads();  // previous group's conv2 reads of rs must finish

    // conv1 + ReLU over region ry=0..33 (global row oy0-1+ry), rx=0..33.
    // Quads of 4 cols: 9 quads per row (last quad cols 32..35 partly scratch,
    // the scratch lanes are never read by conv2).
    for (int i = tid; i < 34 * 9; i += 256) {
      int ry  = i / 9;
      int rx0 = (i - ry * 9) * 4;
      float v[3][6];
#pragma unroll
      for (int dy = 0; dy < 3; dy++) {
        float4 a  = *reinterpret_cast<const float4*>(&xs[ry + dy][rx0]);
        float2 bv = *reinterpret_cast<const float2*>(&xs[ry + dy][rx0 + 4]);
        v[dy][0] = a.x; v[dy][1] = a.y; v[dy][2] = a.z;
        v[dy][3] = a.w; v[dy][4] = bv.x; v[dy][5] = bv.y;
      }
      int gy = oy0 - 1 + ry;
#pragma unroll
      for (int cl = 0; cl < 4; cl++) {
#pragma unroll
        for (int j = 0; j < 4; j++) {
          float s = b1r[cl];
#pragma unroll
          for (int dy = 0; dy < 3; dy++)
#pragma unroll
            for (int dx = 0; dx < 3; dx++)
              s = fmaf(w1r[cl][dy * 3 + dx], v[dy][j + dx], s);
          s = fmaxf(s, 0.f);
          int gx = ox0 - 1 + rx0 + j;
          if ((unsigned)gy >= 256u || (unsigned)gx >= 256u) s = 0.f;  // conv2 zero-pad
          rs[cl][ry][rx0 + j] = s;
        }
      }
    }
    __syncthreads();

    // conv2 partial accumulation for this channel group
    float w2r[4][9];
#pragma unroll
    for (int cl = 0; cl < 4; cl++)
#pragma unroll
      for (int k = 0; k < 9; k++) w2r[cl][k] = w2s[(cg * 4 + cl) * 9 + k];
#pragma unroll
    for (int cl = 0; cl < 4; cl++) {
#pragma unroll
      for (int dy = 0; dy < 3; dy++) {
        const float* rr = &rs[cl][oly + dy][olx0];
        float4 a  = *reinterpret_cast<const float4*>(rr);
        float2 bv = *reinterpret_cast<const float2*>(rr + 4);
        float w0 = w2r[cl][dy * 3], w1v = w2r[cl][dy * 3 + 1], w2v = w2r[cl][dy * 3 + 2];
        acc0 = fmaf(w0, a.x, acc0); acc0 = fmaf(w1v, a.y, acc0); acc0 = fmaf(w2v, a.z, acc0);
        acc1 = fmaf(w0, a.y, acc1); acc1 = fmaf(w1v, a.z, acc1); acc1 = fmaf(w2v, a.w, acc1);
        acc2 = fmaf(w0, a.z, acc2); acc2 = fmaf(w1v, a.w, acc2); acc2 = fmaf(w2v, bv.x, acc2);
        acc3 = fmaf(w0, a.w, acc3); acc3 = fmaf(w1v, bv.x, acc3); acc3 = fmaf(w2v, bv.y, acc3);
      }
    }
  }

  float4 o = make_float4(acc0, acc1, acc2, acc3);
  *reinterpret_cast<float4*>(out + ((size_t)bb * RR + oy0 + oly) * RR + ox0 + olx0) = o;
}

extern "C" void kernel_launch(void* const* d_in, const int* in_sizes, int n_in,
                              void* d_out, int out_size) {
  const float* yt = (const float*)d_in[0];
  const float* Ht = (const float*)d_in[1];
  const float* W1 = (const float*)d_in[2];
  const float* b1 = (const float*)d_in[3];
  const float* W2 = (const float*)d_in[4];
  const float* b2 = (const float*)d_in[5];
  float* out = (float*)d_out;

  stage1_kernel<<<dim3(64, 4), dim3(64, 4)>>>(yt, Ht);
  conv_kernel<<<dim3(8, 8, 32), 256>>>(W1, b1, W2, b2, out);
}